// round 12
// baseline (speedup 1.0000x reference)
#include <cuda_runtime.h>
#include <cstdint>

#define PI_F 3.14159265358979323846f

// gate scratch: [b][ph][pw][e] = [16][16][16][8]
__device__ float g_gate[16 * 16 * 16 * 8];

__device__ __forceinline__ uint64_t pack2(float a) {
    uint64_t r;
    asm("mov.b64 %0, {%1, %1};" : "=l"(r) : "r"(__float_as_uint(a)));
    return r;
}
__device__ __forceinline__ uint64_t fma2(uint64_t a, uint64_t b, uint64_t c) {
    uint64_t d;
    asm("fma.rn.f32x2 %0, %1, %2, %3;" : "=l"(d) : "l"(a), "l"(b), "l"(c));
    return d;
}
__device__ __forceinline__ void unpack2(uint64_t v, float& lo, float& hi) {
    uint32_t l, h;
    asm("mov.b64 {%0, %1}, %2;" : "=r"(l), "=r"(h) : "l"(v));
    lo = __uint_as_float(l);
    hi = __uint_as_float(h);
}
__device__ __forceinline__ void cp4(uint32_t dst_smem, const float* src, bool ok) {
    int sz = ok ? 4 : 0;
    asm volatile("cp.async.ca.shared.global [%0], [%1], 4, %2;"
                 :: "r"(dst_smem), "l"(src), "r"(sz));
}

// ---------------------------------------------------------------------------
// Kernel 1: per-patch gating. One block (256 thr) per patch (B*16*16 = 4096).
// ---------------------------------------------------------------------------
__global__ void gate_kernel(const float* __restrict__ x,
                            const float* __restrict__ gate_w,
                            const float* __restrict__ gate_b) {
    const int blk = blockIdx.x;          // 0..4095
    const int b = blk >> 8;
    const int ph = (blk >> 4) & 15;
    const int pw = blk & 15;
    const int tid = threadIdx.x;

    float part[8];
#pragma unroll
    for (int e = 0; e < 8; e++) part[e] = 0.f;

    const float* xb = x + ((long)b * 64 * 128 + ph * 8) * 128 + pw * 8;

    for (int f = tid; f < 6144; f += 256) {
        int c = f >> 6;
        int r = f & 63;
        float v;
        if (c < 64) {
            int py = r >> 3, px = r & 7;
            v = xb[(c * 128 + py) * 128 + px];
        } else {
            int cc = c - 64;
            int grp = cc >> 3, k = cc & 7;
            float coord = (grp < 2) ? (ph + 0.5f) * (1.f / 16.f)
                                    : (pw + 0.5f) * (1.f / 16.f);
            float ang = coord * ((float)(1 << k) * PI_F);
            v = (grp & 1) ? cosf(ang) : sinf(ang);
        }
#pragma unroll
        for (int e = 0; e < 8; e++) part[e] += v * gate_w[e * 6144 + f];
    }

#pragma unroll
    for (int off = 16; off; off >>= 1) {
#pragma unroll
        for (int e = 0; e < 8; e++)
            part[e] += __shfl_down_sync(0xffffffffu, part[e], off);
    }

    __shared__ float s_red[8][8];
    __shared__ float s_logit[8];
    const int warp = tid >> 5, lane = tid & 31;
    if (lane == 0) {
#pragma unroll
        for (int e = 0; e < 8; e++) s_red[warp][e] = part[e];
    }
    __syncthreads();
    if (tid < 8) {
        float s = gate_b[tid];
#pragma unroll
        for (int w = 0; w < 8; w++) s += s_red[w][tid];
        s_logit[tid] = s;
    }
    __syncthreads();
    if (tid < 8) {
        float m = s_logit[0];
#pragma unroll
        for (int e = 1; e < 8; e++) m = fmaxf(m, s_logit[e]);
        float den = 0.f;
#pragma unroll
        for (int e = 0; e < 8; e++) den += expf(s_logit[e] - m);
        g_gate[blk * 8 + tid] = expf(s_logit[tid] - m) / den;
    }
}

// ---------------------------------------------------------------------------
// Kernel 2: fused 8-expert conv3x3 + bias + relu + gated combine.
// Block: batch b, 16x16 pixel tile, 8 base output channels x 8 experts
// (M = 64 conv channels). 256 threads: warp = base channel bl (weights are
// warp-uniform LDS.128 broadcasts); lane: r = lane&15 (row), q = lane>>4
// (col half) -> conflict-free activation LDS.64 (words r*18 mod 32 distinct
// per 16-lane phase). Thread tile: 8 pixels x 8 experts = 32 f32x2 accs.
// K chunked by 8 channels, double-buffered via cp.async (halo zero-filled
// with zfill). Epilogue combines experts in-register -> single store.
// ---------------------------------------------------------------------------
static constexpr int IN_CH_FLOATS = 8 * 324;   // 2592 per buffer
static constexpr int W_CH_FLOATS  = 8 * 576;   // 4608 per buffer
static constexpr int BUF_FLOATS   = IN_CH_FLOATS + W_CH_FLOATS;
static constexpr int SMEM_BYTES   = 2 * BUF_FLOATS * 4;   // 57600

__global__ void __launch_bounds__(256, 2)
conv_kernel(const float* __restrict__ x,
            const float* __restrict__ ew,   // [8][64][64][3][3]
            const float* __restrict__ eb,   // [8][64]
            float* __restrict__ out) {
    extern __shared__ __align__(16) float smem[];
    // layout: [2 bufs][ in: 8*324 | w: 8*576 ]
    __shared__ float g_s[4][8];                         // [patch-in-tile][e]

    const int tid = threadIdx.x;
    const int tileid = blockIdx.x;       // 0..63
    const int tx = tileid & 7, ty = tileid >> 3;
    const int grp = blockIdx.y;          // base channels grp*8 .. grp*8+7
    const int b = blockIdx.z;

    if (tid < 32) {
        int pp = tid >> 3, e = tid & 7;
        int ph = ty * 2 + (pp >> 1), pw = tx * 2 + (pp & 1);
        g_s[pp][e] = g_gate[((b * 16 + ph) * 16 + pw) * 8 + e];
    }

    const int bl = tid >> 5;             // 0..7 : base channel (== warp id)
    const int lane = tid & 31;
    const int r = lane & 15;             // pixel row 0..15
    const int q = lane >> 4;             // half: cols 8q..8q+7

    const int y0 = ty * 16, x0 = tx * 16;
    const int bc = grp * 8 + bl;

    const float* xb = x + (long)b * 64 * 128 * 128;
    const uint32_t smem_u32 = (uint32_t)__cvta_generic_to_shared(smem);

    // ---- prefetch of one K-chunk (8 input channels) into buffer `buf` ----
    auto prefetch = [&](int c0, int buf) {
        uint32_t in_dst = smem_u32 + (buf * BUF_FLOATS) * 4;
        uint32_t w_dst  = in_dst + IN_CH_FLOATS * 4;
        // input tile: 8 ch x 18x18 (halo zero-filled via zfill)
        for (int idx = tid; idx < IN_CH_FLOATS; idx += 256) {
            int c = idx / 324;
            int rem = idx - c * 324;
            int iy = rem / 18;
            int ix = rem - iy * 18;
            int gy = y0 + iy - 1, gx = x0 + ix - 1;
            bool ok = ((unsigned)gy < 128u) && ((unsigned)gx < 128u);
            const float* src = ok ? xb + ((c0 + c) * 128 + gy) * 128 + gx : xb;
            cp4(in_dst + idx * 4, src, ok);
        }
        // weights: [cl][tap][m], m = blw*8 + e
        for (int idx = tid; idx < W_CH_FLOATS; idx += 256) {
            int cl = idx / 576;
            int rem = idx - cl * 576;
            int tap = rem >> 6;
            int m = rem & 63;
            int blw = m >> 3, e = m & 7;
            const float* src =
                ew + ((e * 64 + grp * 8 + blw) * 64 + c0 + cl) * 9 + tap;
            cp4(w_dst + idx * 4, src, true);
        }
        asm volatile("cp.async.commit_group;");
    };

    uint64_t acc[8][4];                  // [pixel][expert-pair]
#pragma unroll
    for (int p = 0; p < 8; p++)
#pragma unroll
        for (int ep = 0; ep < 4; ep++) acc[p][ep] = 0ull;

    prefetch(0, 0);

#pragma unroll 1
    for (int i = 0; i < 8; i++) {
        asm volatile("cp.async.wait_group 0;");
        __syncthreads();
        if (i < 7) prefetch((i + 1) * 8, (i + 1) & 1);

        const float* in_s = smem + (i & 1) * BUF_FLOATS;
        const float* ws   = in_s + IN_CH_FLOATS;

#pragma unroll 1
        for (int cl = 0; cl < 8; cl++) {
            const float2* abase = reinterpret_cast<const float2*>(
                in_s + cl * 324 + r * 18 + q * 8);
            const float* wbase = ws + cl * 576 + bl * 8;
#pragma unroll
            for (int dy = 0; dy < 3; dy++) {
                float2 v0 = abase[dy * 9 + 0];
                float2 v1 = abase[dy * 9 + 1];
                float2 v2 = abase[dy * 9 + 2];
                float2 v3 = abase[dy * 9 + 3];
                float2 v4 = abase[dy * 9 + 4];
                uint64_t ap[10];
                ap[0] = pack2(v0.x); ap[1] = pack2(v0.y);
                ap[2] = pack2(v1.x); ap[3] = pack2(v1.y);
                ap[4] = pack2(v2.x); ap[5] = pack2(v2.y);
                ap[6] = pack2(v3.x); ap[7] = pack2(v3.y);
                ap[8] = pack2(v4.x); ap[9] = pack2(v4.y);
#pragma unroll
                for (int dx = 0; dx < 3; dx++) {
                    const ulonglong2* wq =
                        reinterpret_cast<const ulonglong2*>(
                            wbase + (dy * 3 + dx) * 64);
                    ulonglong2 wab = wq[0];   // expert pairs 0,1 (LDS.128)
                    ulonglong2 wcd = wq[1];   // expert pairs 2,3 (LDS.128)
#pragma unroll
                    for (int p = 0; p < 8; p++) {
                        uint64_t a = ap[dx + p];
                        acc[p][0] = fma2(wab.x, a, acc[p][0]);
                        acc[p][1] = fma2(wab.y, a, acc[p][1]);
                        acc[p][2] = fma2(wcd.x, a, acc[p][2]);
                        acc[p][3] = fma2(wcd.y, a, acc[p][3]);
                    }
                }
            }
        }
        __syncthreads();
    }

    // epilogue: bias + relu + gated combine over 8 experts, single store
    const int pp = ((r >> 3) << 1) + q;   // patch within tile
    float gv[8], bias[8];
#pragma unroll
    for (int e = 0; e < 8; e++) {
        gv[e] = g_s[pp][e];
        bias[e] = eb[e * 64 + bc];
    }

    float o[8];
#pragma unroll
    for (int p = 0; p < 8; p++) {
        float s = 0.f;
#pragma unroll
        for (int ep = 0; ep < 4; ep++) {
            float ylo, yhi;
            unpack2(acc[p][ep], ylo, yhi);
            int e0 = 2 * ep, e1 = 2 * ep + 1;
            s += gv[e0] * fmaxf(ylo + bias[e0], 0.f);
            s += gv[e1] * fmaxf(yhi + bias[e1], 0.f);
        }
        o[p] = s;
    }
    float* op = out + (((long)(b * 64 + bc) * 128 + y0 + r) * 128 + x0 + q * 8);
    reinterpret_cast<float4*>(op)[0] = make_float4(o[0], o[1], o[2], o[3]);
    reinterpret_cast<float4*>(op)[1] = make_float4(o[4], o[5], o[6], o[7]);
}

extern "C" void kernel_launch(void* const* d_in, const int* in_sizes, int n_in,
                              void* d_out, int out_size) {
    const float* x  = (const float*)d_in[0];   // [16,64,128,128]
    const float* ew = (const float*)d_in[1];   // [8,64,64,3,3]
    const float* eb = (const float*)d_in[2];   // [8,64]
    const float* gw = (const float*)d_in[3];   // [8,6144]
    const float* gb = (const float*)d_in[4];   // [8]
    float* out = (float*)d_out;                // [16,64,128,128]

    static bool attr_set = false;
    if (!attr_set) {
        cudaFuncSetAttribute(conv_kernel,
                             cudaFuncAttributeMaxDynamicSharedMemorySize,
                             SMEM_BYTES);
        attr_set = true;
    }

    gate_kernel<<<4096, 256>>>(x, gw, gb);

    dim3 grid(64, 8, 16);  // (spatial tile, oc group of 8, batch)
    conv_kernel<<<grid, 256, SMEM_BYTES>>>(x, ew, eb, out);
}

// round 13
// speedup vs baseline: 1.3690x; 1.3690x over previous
#include <cuda_runtime.h>
#include <cstdint>

#define PI_F 3.14159265358979323846f

// scratch (__device__ globals: the sanctioned no-alloc workaround)
__device__ float g_gate[16 * 16 * 16 * 8];                 // [b][ph][pw][e]
__device__ float g_xpad[16 * 64 * 130 * 132];              // zero-halo input
__device__ float g_wr[8 * 64 * 9 * 64];                    // [grp][c][tap][m]

__device__ __forceinline__ uint64_t pack2(float a) {
    uint64_t r;
    asm("mov.b64 %0, {%1, %1};" : "=l"(r) : "r"(__float_as_uint(a)));
    return r;
}
__device__ __forceinline__ uint64_t fma2(uint64_t a, uint64_t b, uint64_t c) {
    uint64_t d;
    asm("fma.rn.f32x2 %0, %1, %2, %3;" : "=l"(d) : "l"(a), "l"(b), "l"(c));
    return d;
}
__device__ __forceinline__ void unpack2(uint64_t v, float& lo, float& hi) {
    uint32_t l, h;
    asm("mov.b64 {%0, %1}, %2;" : "=r"(l), "=r"(h) : "l"(v));
    lo = __uint_as_float(l);
    hi = __uint_as_float(h);
}
__device__ __forceinline__ void cp8(uint32_t dst, const float* src) {
    asm volatile("cp.async.ca.shared.global [%0], [%1], 8;"
                 :: "r"(dst), "l"(src));
}
__device__ __forceinline__ void cp16(uint32_t dst, const float* src) {
    asm volatile("cp.async.ca.shared.global [%0], [%1], 16;"
                 :: "r"(dst), "l"(src));
}

// ---------------------------------------------------------------------------
// Kernel 0a: zero-halo pad of x into g_xpad [16][64][130][132]
// ---------------------------------------------------------------------------
__global__ void pad_kernel(const float* __restrict__ x) {
    int idx = blockIdx.x * 256 + threadIdx.x;               // < 17,571,840
    int xp = idx % 132;
    int t = idx / 132;
    int yp = t % 130;
    int bc = t / 130;                                       // b*64 + c
    float v = 0.f;
    if (xp >= 1 && xp <= 128 && yp >= 1 && yp <= 128)
        v = x[((long)bc * 128 + (yp - 1)) * 128 + (xp - 1)];
    g_xpad[idx] = v;
}

// ---------------------------------------------------------------------------
// Kernel 0b: weight restage ew[8][64][64][3][3] -> g_wr[grp][c][tap][m]
//            m = blw*8 + e  (blw = base channel within group of 8)
// ---------------------------------------------------------------------------
__global__ void wrestage_kernel(const float* __restrict__ ew) {
    int idx = blockIdx.x * 256 + threadIdx.x;               // < 294,912
    int m = idx & 63;
    int t = idx >> 6;
    int tap = t % 9;
    t /= 9;
    int c = t & 63;
    int grp = t >> 6;
    int e = m & 7, blw = m >> 3;
    g_wr[idx] = ew[((e * 64 + grp * 8 + blw) * 64 + c) * 9 + tap];
}

// ---------------------------------------------------------------------------
// Kernel 1: per-patch gating. One block (256 thr) per patch (B*16*16 = 4096).
// ---------------------------------------------------------------------------
__global__ void gate_kernel(const float* __restrict__ x,
                            const float* __restrict__ gate_w,
                            const float* __restrict__ gate_b) {
    const int blk = blockIdx.x;          // 0..4095
    const int b = blk >> 8;
    const int ph = (blk >> 4) & 15;
    const int pw = blk & 15;
    const int tid = threadIdx.x;

    float part[8];
#pragma unroll
    for (int e = 0; e < 8; e++) part[e] = 0.f;

    const float* xb = x + ((long)b * 64 * 128 + ph * 8) * 128 + pw * 8;

    for (int f = tid; f < 6144; f += 256) {
        int c = f >> 6;
        int r = f & 63;
        float v;
        if (c < 64) {
            int py = r >> 3, px = r & 7;
            v = xb[(c * 128 + py) * 128 + px];
        } else {
            int cc = c - 64;
            int grp = cc >> 3, k = cc & 7;
            float coord = (grp < 2) ? (ph + 0.5f) * (1.f / 16.f)
                                    : (pw + 0.5f) * (1.f / 16.f);
            float ang = coord * ((float)(1 << k) * PI_F);
            v = (grp & 1) ? cosf(ang) : sinf(ang);
        }
#pragma unroll
        for (int e = 0; e < 8; e++) part[e] += v * gate_w[e * 6144 + f];
    }

#pragma unroll
    for (int off = 16; off; off >>= 1) {
#pragma unroll
        for (int e = 0; e < 8; e++)
            part[e] += __shfl_down_sync(0xffffffffu, part[e], off);
    }

    __shared__ float s_red[8][8];
    __shared__ float s_logit[8];
    const int warp = tid >> 5, lane = tid & 31;
    if (lane == 0) {
#pragma unroll
        for (int e = 0; e < 8; e++) s_red[warp][e] = part[e];
    }
    __syncthreads();
    if (tid < 8) {
        float s = gate_b[tid];
#pragma unroll
        for (int w = 0; w < 8; w++) s += s_red[w][tid];
        s_logit[tid] = s;
    }
    __syncthreads();
    if (tid < 8) {
        float m = s_logit[0];
#pragma unroll
        for (int e = 1; e < 8; e++) m = fmaxf(m, s_logit[e]);
        float den = 0.f;
#pragma unroll
        for (int e = 0; e < 8; e++) den += expf(s_logit[e] - m);
        g_gate[blk * 8 + tid] = expf(s_logit[tid] - m) / den;
    }
}

// ---------------------------------------------------------------------------
// Kernel 2: fused 8-expert conv3x3 + bias + relu + gated combine.
// Block: batch b, 16x16 pixel tile, 8 base oc x 8 experts (M=64).
// Warp = base channel (weights warp-uniform LDS.128 broadcast); lane:
// r = lane&15 (row), q = lane>>4 (col half) -> conflict-free LDS.64.
// Thread: 8 pixels x 8 experts = 32 f32x2 accumulators.
// K chunked by 8 channels, double-buffered: input via 8B cp.async from
// pre-padded g_xpad (no predicates), weights via 16B cp.async from g_wr
// (fully contiguous chunk). Epilogue combines experts in-register.
// ---------------------------------------------------------------------------
static constexpr int IN_CH_FLOATS = 8 * 324;   // 2592 per buffer
static constexpr int W_CH_FLOATS  = 8 * 576;   // 4608 per buffer
static constexpr int BUF_FLOATS   = IN_CH_FLOATS + W_CH_FLOATS;   // 7200
static constexpr int SMEM_BYTES   = 2 * BUF_FLOATS * 4;           // 57600

__global__ void __launch_bounds__(256, 2)
conv_kernel(const float* __restrict__ eb,   // [8][64]
            float* __restrict__ out) {
    extern __shared__ __align__(16) float smem[];
    __shared__ float g_s[4][8];

    const int tid = threadIdx.x;
    const int tileid = blockIdx.x;       // 0..63
    const int tx = tileid & 7, ty = tileid >> 3;
    const int grp = blockIdx.y;          // base channels grp*8 .. grp*8+7
    const int b = blockIdx.z;

    if (tid < 32) {
        int pp = tid >> 3, e = tid & 7;
        int ph = ty * 2 + (pp >> 1), pw = tx * 2 + (pp & 1);
        g_s[pp][e] = g_gate[((b * 16 + ph) * 16 + pw) * 8 + e];
    }

    const int bl = tid >> 5;             // warp id = base channel
    const int lane = tid & 31;
    const int r = lane & 15;             // pixel row 0..15
    const int q = lane >> 4;             // half: cols 8q..8q+7

    const int y0 = ty * 16, x0 = tx * 16;
    const int bc = grp * 8 + bl;

    const uint32_t smem_u32 = (uint32_t)__cvta_generic_to_shared(smem);
    // padded input base for this (b, tile): rows y0.., cols x0..
    const float* xp = g_xpad + ((long)b * 64 * 130) * 132 + (long)y0 * 132 + x0;
    const float* wr = g_wr + (long)grp * 64 * 576;   // [c][tap][m] slice

    auto prefetch = [&](int c0, int buf) {
        uint32_t in_dst = smem_u32 + (buf * BUF_FLOATS) * 4;
        uint32_t w_dst  = in_dst + IN_CH_FLOATS * 4;
        // input: 8 ch x 18 rows x 9 cp8 (18 floats/row) = 1296
        for (int idx = tid; idx < 1296; idx += 256) {
            int j = idx % 9;
            int t = idx / 9;
            int iy = t % 18;
            int c = t / 18;
            const float* src = xp + ((long)(c0 + c) * 130 + iy) * 132 + 2 * j;
            cp8(in_dst + (c * 324 + iy * 18 + 2 * j) * 4, src);
        }
        // weights: contiguous 4608 floats = 1152 cp16
        const float* wsrc = wr + c0 * 576;
        for (int idx = tid; idx < 1152; idx += 256)
            cp16(w_dst + idx * 16, wsrc + idx * 4);
        asm volatile("cp.async.commit_group;");
    };

    uint64_t acc[8][4];
#pragma unroll
    for (int p = 0; p < 8; p++)
#pragma unroll
        for (int ep = 0; ep < 4; ep++) acc[p][ep] = 0ull;

    prefetch(0, 0);

#pragma unroll 1
    for (int i = 0; i < 8; i++) {
        asm volatile("cp.async.wait_group 0;");
        __syncthreads();
        if (i < 7) prefetch((i + 1) * 8, (i + 1) & 1);

        const float* in_s = smem + (i & 1) * BUF_FLOATS;
        const float* ws   = in_s + IN_CH_FLOATS;

#pragma unroll 1
        for (int cl = 0; cl < 8; cl++) {
            const float2* abase = reinterpret_cast<const float2*>(
                in_s + cl * 324 + r * 18 + q * 8);
            const float* wbase = ws + cl * 576 + bl * 8;
#pragma unroll
            for (int dy = 0; dy < 3; dy++) {
                float2 v0 = abase[dy * 9 + 0];
                float2 v1 = abase[dy * 9 + 1];
                float2 v2 = abase[dy * 9 + 2];
                float2 v3 = abase[dy * 9 + 3];
                float2 v4 = abase[dy * 9 + 4];
                uint64_t ap[10];
                ap[0] = pack2(v0.x); ap[1] = pack2(v0.y);
                ap[2] = pack2(v1.x); ap[3] = pack2(v1.y);
                ap[4] = pack2(v2.x); ap[5] = pack2(v2.y);
                ap[6] = pack2(v3.x); ap[7] = pack2(v3.y);
                ap[8] = pack2(v4.x); ap[9] = pack2(v4.y);
#pragma unroll
                for (int dx = 0; dx < 3; dx++) {
                    const ulonglong2* wq =
                        reinterpret_cast<const ulonglong2*>(
                            wbase + (dy * 3 + dx) * 64);
                    ulonglong2 wab = wq[0];   // expert pairs 0,1
                    ulonglong2 wcd = wq[1];   // expert pairs 2,3
#pragma unroll
                    for (int p = 0; p < 8; p++) {
                        uint64_t a = ap[dx + p];
                        acc[p][0] = fma2(wab.x, a, acc[p][0]);
                        acc[p][1] = fma2(wab.y, a, acc[p][1]);
                        acc[p][2] = fma2(wcd.x, a, acc[p][2]);
                        acc[p][3] = fma2(wcd.y, a, acc[p][3]);
                    }
                }
            }
        }
        __syncthreads();
    }

    // epilogue: bias + relu + gated combine over 8 experts, single store
    const int pp = ((r >> 3) << 1) + q;
    float gv[8], bias[8];
#pragma unroll
    for (int e = 0; e < 8; e++) {
        gv[e] = g_s[pp][e];
        bias[e] = eb[e * 64 + bc];
    }

    float o[8];
#pragma unroll
    for (int p = 0; p < 8; p++) {
        float s = 0.f;
#pragma unroll
        for (int ep = 0; ep < 4; ep++) {
            float ylo, yhi;
            unpack2(acc[p][ep], ylo, yhi);
            int e0 = 2 * ep, e1 = 2 * ep + 1;
            s += gv[e0] * fmaxf(ylo + bias[e0], 0.f);
            s += gv[e1] * fmaxf(yhi + bias[e1], 0.f);
        }
        o[p] = s;
    }
    float* op = out + (((long)(b * 64 + bc) * 128 + y0 + r) * 128 + x0 + q * 8);
    reinterpret_cast<float4*>(op)[0] = make_float4(o[0], o[1], o[2], o[3]);
    reinterpret_cast<float4*>(op)[1] = make_float4(o[4], o[5], o[6], o[7]);
}

extern "C" void kernel_launch(void* const* d_in, const int* in_sizes, int n_in,
                              void* d_out, int out_size) {
    const float* x  = (const float*)d_in[0];   // [16,64,128,128]
    const float* ew = (const float*)d_in[1];   // [8,64,64,3,3]
    const float* eb = (const float*)d_in[2];   // [8,64]
    const float* gw = (const float*)d_in[3];   // [8,6144]
    const float* gb = (const float*)d_in[4];   // [8]
    float* out = (float*)d_out;                // [16,64,128,128]

    static bool attr_set = false;
    if (!attr_set) {
        cudaFuncSetAttribute(conv_kernel,
                             cudaFuncAttributeMaxDynamicSharedMemorySize,
                             SMEM_BYTES);
        attr_set = true;
    }

    pad_kernel<<<(16 * 64 * 130 * 132) / 256, 256>>>(x);
    wrestage_kernel<<<(8 * 64 * 9 * 64) / 256, 256>>>(ew);
    gate_kernel<<<4096, 256>>>(x, gw, gb);

    dim3 grid(64, 8, 16);  // (spatial tile, oc group of 8, batch)
    conv_kernel<<<grid, 256, SMEM_BYTES>>>(eb, out);
}

// round 15
// speedup vs baseline: 2.2818x; 1.6668x over previous
#include <cuda_runtime.h>
#include <cuda_bf16.h>
#include <cstdint>

#define PI_F 3.14159265358979323846f

// ---------------- device scratch (__device__ globals: sanctioned) ----------
__device__ float g_gate[16 * 16 * 16 * 8];                            // [b][ph][pw][e]
__device__ __align__(128) __nv_bfloat16 g_xh[16ULL * 130 * 130 * 64]; // NHWC hi
__device__ __align__(128) __nv_bfloat16 g_xl[16ULL * 130 * 130 * 64]; // NHWC lo
__device__ __align__(128) __nv_bfloat16 g_wA[9 * 4 * 2 * 128 * 64];   // [tap][mb][pl][ml][c]

// ---------------- PTX helpers (all plain sm_80+ ISA, compute_103-safe) -----
__device__ __forceinline__ void cp16(uint32_t dst, const void* src) {
    asm volatile("cp.async.ca.shared.global [%0], [%1], 16;"
                 :: "r"(dst), "l"(src) : "memory");
}
__device__ __forceinline__ void ldsm4(uint32_t* r, uint32_t addr) {
    asm volatile("ldmatrix.sync.aligned.m8n8.x4.shared.b16 {%0,%1,%2,%3}, [%4];"
                 : "=r"(r[0]), "=r"(r[1]), "=r"(r[2]), "=r"(r[3])
                 : "r"(addr));
}
__device__ __forceinline__ void mma16816(float* c, const uint32_t* a,
                                         const uint32_t* b) {
    asm volatile(
        "mma.sync.aligned.m16n8k16.row.col.f32.bf16.bf16.f32 "
        "{%0,%1,%2,%3}, {%4,%5,%6,%7}, {%8,%9}, {%0,%1,%2,%3};"
        : "+f"(c[0]), "+f"(c[1]), "+f"(c[2]), "+f"(c[3])
        : "r"(a[0]), "r"(a[1]), "r"(a[2]), "r"(a[3]), "r"(b[0]), "r"(b[1]));
}

// ---------------------------------------------------------------------------
// prep_x: x[b][c][y][x] fp32 -> padded NHWC bf16 hi/lo: [b][yp 130][xp 130][c]
// ---------------------------------------------------------------------------
__global__ void prep_x(const float* __restrict__ x) {
    __shared__ float tile[64][128];
    const int yp = blockIdx.x;       // 0..129
    const int b = blockIdx.y;
    const int tid = threadIdx.x;
    const bool rowok = (yp >= 1 && yp <= 128);
    if (rowok) {
        const float* src = x + ((size_t)b * 64 * 128 + (yp - 1)) * 128;
        for (int i = tid; i < 8192; i += 256) {
            int c = i >> 7, xx = i & 127;
            tile[c][xx] = src[c * 16384 + xx];
        }
    }
    __syncthreads();
    const size_t obase = ((size_t)b * 130 + yp) * 130 * 64;
    for (int i = tid; i < 130 * 64; i += 256) {
        int xp = i >> 6, c = i & 63;
        float v = 0.f;
        if (rowok && xp >= 1 && xp <= 128) v = tile[c][xp - 1];
        __nv_bfloat16 hi = __float2bfloat16(v);
        __nv_bfloat16 lo = __float2bfloat16(v - __bfloat162float(hi));
        g_xh[obase + i] = hi;
        g_xl[obase + i] = lo;
    }
}

// ---------------------------------------------------------------------------
// prep_w: ew[e][oc][c][dy][dx] -> g_wA[tap][mb][plane][ml][c] bf16 hi/lo
//         ml = eloc*64 + oc,  e = mb*2 + eloc
// ---------------------------------------------------------------------------
__global__ void prep_w(const float* __restrict__ ew) {
    int idx = blockIdx.x * 256 + threadIdx.x;   // < 294912
    int c = idx & 63;
    int ml = (idx >> 6) & 127;
    int mb = (idx >> 13) & 3;
    int tap = idx >> 15;
    int e = mb * 2 + (ml >> 6);
    int oc = ml & 63;
    int dy = tap / 3, dx = tap % 3;
    float w = ew[(((e * 64 + oc) * 64 + c) * 3 + dy) * 3 + dx];
    __nv_bfloat16 hi = __float2bfloat16(w);
    __nv_bfloat16 lo = __float2bfloat16(w - __bfloat162float(hi));
    size_t o = (size_t)(tap * 4 + mb) * 16384 + ml * 64 + c;
    g_wA[o] = hi;             // plane 0
    g_wA[o + 8192] = lo;      // plane 1
}

// ---------------------------------------------------------------------------
// gate kernel (proven correct, ~60us)
// ---------------------------------------------------------------------------
__global__ void gate_kernel(const float* __restrict__ x,
                            const float* __restrict__ gate_w,
                            const float* __restrict__ gate_b) {
    const int blk = blockIdx.x;
    const int b = blk >> 8;
    const int ph = (blk >> 4) & 15;
    const int pw = blk & 15;
    const int tid = threadIdx.x;

    float part[8];
#pragma unroll
    for (int e = 0; e < 8; e++) part[e] = 0.f;

    const float* xb = x + ((size_t)b * 64 * 128 + ph * 8) * 128 + pw * 8;

    for (int f = tid; f < 6144; f += 256) {
        int c = f >> 6;
        int r = f & 63;
        float v;
        if (c < 64) {
            int py = r >> 3, px = r & 7;
            v = xb[(c * 128 + py) * 128 + px];
        } else {
            int cc = c - 64;
            int grp = cc >> 3, k = cc & 7;
            float coord = (grp < 2) ? (ph + 0.5f) * (1.f / 16.f)
                                    : (pw + 0.5f) * (1.f / 16.f);
            float ang = coord * ((float)(1 << k) * PI_F);
            v = (grp & 1) ? cosf(ang) : sinf(ang);
        }
#pragma unroll
        for (int e = 0; e < 8; e++) part[e] += v * gate_w[e * 6144 + f];
    }

#pragma unroll
    for (int off = 16; off; off >>= 1) {
#pragma unroll
        for (int e = 0; e < 8; e++)
            part[e] += __shfl_down_sync(0xffffffffu, part[e], off);
    }

    __shared__ float s_red[8][8];
    __shared__ float s_logit[8];
    const int warp = tid >> 5, lane = tid & 31;
    if (lane == 0) {
#pragma unroll
        for (int e = 0; e < 8; e++) s_red[warp][e] = part[e];
    }
    __syncthreads();
    if (tid < 8) {
        float s = gate_b[tid];
#pragma unroll
        for (int w = 0; w < 8; w++) s += s_red[w][tid];
        s_logit[tid] = s;
    }
    __syncthreads();
    if (tid < 8) {
        float m = s_logit[0];
#pragma unroll
        for (int e = 1; e < 8; e++) m = fmaxf(m, s_logit[e]);
        float den = 0.f;
#pragma unroll
        for (int e = 0; e < 8; e++) den += expf(s_logit[e] - m);
        g_gate[blk * 8 + tid] = expf(s_logit[tid] - m) / den;
    }
}

// ---------------------------------------------------------------------------
// conv_mma: HMMA (mma.sync bf16) implicit-GEMM conv + bias + relu + gated
// combine. CTA = (row y, batch b): N = 128 pixels, M = 128 per phase, 4
// mblock phases (2 experts each) x 9 taps = 36 double-buffered stages.
// Warp grid 2(M) x 4(N); warp tile M64 x N32 -> 16 mma tiles, 64 fp32 acc.
// 3 hi/lo passes per k16: Wh*Xh + Wl*Xh + Wh*Xl. Per-phase epilogue folds
// bias+relu+gate into a 64KB SMEM accumulator (per-thread slots, race-free);
// final sum over expert-parity planes -> single float4 store. No atomics.
// SMEM (dyn): A0|A1 (32KB ea) | B0|B1 (32KB ea) | acc 64KB.
// Swizzle: chunk j of row r stored at r*128 + ((j^(r&7))<<4)  (conflict-free
// for both cp.async stores and ldmatrix reads).
// ---------------------------------------------------------------------------
static constexpr int SACC_OFF = 131072;
static constexpr int DSMEM_BYTES = 131072 + 65536 + 1024;   // 197632

__global__ void __launch_bounds__(256, 1)
conv_mma(const float* __restrict__ eb, float* __restrict__ out) {
    extern __shared__ char dsm_raw[];
    __shared__ float sg[1024];      // [e][x]
    __shared__ float sbias[512];    // [e*64+oc]

    const int tid = threadIdx.x;
    const int wid = tid >> 5;
    const int lane = tid & 31;
    const int y = blockIdx.x;
    const int b = blockIdx.y;
    const int wm = wid >> 2;        // 0..1 : M half
    const int wn = wid & 3;         // 0..3 : N quarter

    uint32_t base0 = (uint32_t)__cvta_generic_to_shared(dsm_raw);
    const uint32_t base = (base0 + 1023) & ~1023u;
    float* sacc = reinterpret_cast<float*>(dsm_raw + (base - base0) + SACC_OFF);

    for (int i = tid; i < 1024; i += 256) {
        int e = i >> 7, xx = i & 127;
        sg[i] = g_gate[(((b * 16 + (y >> 3)) * 16 + (xx >> 3)) << 3) + e];
    }
    for (int i = tid; i < 512; i += 256) sbias[i] = eb[i];
    for (int i = tid; i < 16384; i += 256) sacc[i] = 0.f;

    auto prefetch = [&](int s) {
        const int mb = s / 9, tap = s % 9;
        // A: W[tap][mb] hi/lo, contiguous 32KB in g_wA
        uint32_t abuf = base + (s & 1) * 32768;
        const __nv_bfloat16* asrc = g_wA + (size_t)(tap * 4 + mb) * 16384;
        for (int i = tid; i < 2048; i += 256) {
            int row = i >> 3, j = i & 7;          // row = plane*128 + ml
            cp16(abuf + row * 128 + ((j ^ (row & 7)) << 4),
                 asrc + row * 64 + j * 8);
        }
        // B: X row (y+dy), pixels dx..dx+127, hi/lo planes
        uint32_t bbuf = base + 65536 + (s & 1) * 32768;
        const int dy = tap / 3, dx = tap % 3;
        const size_t xoff = (((size_t)b * 130 + (y + dy)) * 130 + dx) * 64;
        for (int i = tid; i < 2048; i += 256) {
            int row = i >> 3, j = i & 7;          // row = plane*128 + pixel
            int plane = row >> 7, p = row & 127;
            const __nv_bfloat16* src =
                (plane ? g_xl : g_xh) + xoff + (size_t)p * 64 + j * 8;
            cp16(bbuf + row * 128 + ((j ^ (row & 7)) << 4), src);
        }
        asm volatile("cp.async.commit_group;" ::: "memory");
    };

    float acc[4][4][4];
#pragma unroll
    for (int mt = 0; mt < 4; mt++)
#pragma unroll
        for (int nt = 0; nt < 4; nt++)
#pragma unroll
            for (int v = 0; v < 4; v++) acc[mt][nt][v] = 0.f;

    const int lo4 = lane & 15;      // A: row selector within m16
    const int hi4 = lane >> 4;      // A: k-chunk selector / B: pixel+8 sel

    prefetch(0);

#pragma unroll 1
    for (int s = 0; s < 36; s++) {
        if (s + 1 < 36) {
            prefetch(s + 1);
            asm volatile("cp.async.wait_group 1;" ::: "memory");
        } else {
            asm volatile("cp.async.wait_group 0;" ::: "memory");
        }
        __syncthreads();

        const uint32_t ab = base + (s & 1) * 32768;
        const uint32_t bb = base + 65536 + (s & 1) * 32768;

#pragma unroll
        for (int kk = 0; kk < 4; kk++) {          // k0 = kk*16
            const int j0 = kk * 2;                // 16B chunk of k0
            uint32_t Ah[4][4], Al[4][4];
#pragma unroll
            for (int mt = 0; mt < 4; mt++) {
                int row = wm * 64 + mt * 16 + lo4;
                uint32_t off =
                    row * 128 + (((j0 + hi4) ^ (row & 7)) << 4);
                ldsm4(Ah[mt], ab + off);
                ldsm4(Al[mt], ab + 16384 + off);
            }
            uint32_t Bh[8], Bl[8];
#pragma unroll
            for (int half = 0; half < 2; half++) {
                int p = wn * 32 + half * 16 + (lane & 7) + hi4 * 8;
                int ch = j0 + ((lane >> 3) & 1);
                uint32_t off = p * 128 + ((ch ^ (p & 7)) << 4);
                ldsm4(Bh + half * 4, bb + off);
                ldsm4(Bl + half * 4, bb + 16384 + off);
            }
#pragma unroll
            for (int mt = 0; mt < 4; mt++) {
#pragma unroll
                for (int nt = 0; nt < 4; nt++) {
                    mma16816(acc[mt][nt], Ah[mt], Bh + nt * 2);
                    mma16816(acc[mt][nt], Al[mt], Bh + nt * 2);
                    mma16816(acc[mt][nt], Ah[mt], Bl + nt * 2);
                }
            }
        }
        __syncthreads();

        if (s % 9 == 8) {
            // per-mblock epilogue: bias + relu + gate into sacc, reset acc
            const int mb = s / 9;
#pragma unroll
            for (int mt = 0; mt < 4; mt++) {
                int mrow0 = wm * 64 + mt * 16 + (lane >> 2);
#pragma unroll
                for (int half = 0; half < 2; half++) {
                    int m = mrow0 + half * 8;
                    int eloc = m >> 6, oc = m & 63;
                    int e = mb * 2 + eloc;
                    float bias = sbias[e * 64 + oc];
                    const float* grow = sg + e * 128;
                    float* arow = sacc + eloc * 8192 + oc * 128;
#pragma unroll
                    for (int nt = 0; nt < 4; nt++) {
                        int n = wn * 32 + nt * 8 + (lane & 3) * 2;
                        float v0 = acc[mt][nt][half * 2 + 0];
                        float v1 = acc[mt][nt][half * 2 + 1];
                        arow[n]     += grow[n]     * fmaxf(v0 + bias, 0.f);
                        arow[n + 1] += grow[n + 1] * fmaxf(v1 + bias, 0.f);
                        acc[mt][nt][half * 2 + 0] = 0.f;
                        acc[mt][nt][half * 2 + 1] = 0.f;
                    }
                }
            }
        }
    }

    __syncthreads();
    const size_t ob = (size_t)b * 64 * 16384 + (size_t)y * 128;
    for (int i = tid; i < 2048; i += 256) {     // 64 oc x 32 float4
        int oc2 = i >> 5, j = i & 31;
        const float* r0 = sacc + oc2 * 128 + j * 4;
        const float* r1 = r0 + 8192;
        float4 v;
        v.x = r0[0] + r1[0];
        v.y = r0[1] + r1[1];
        v.z = r0[2] + r1[2];
        v.w = r0[3] + r1[3];
        *reinterpret_cast<float4*>(out + ob + (size_t)oc2 * 16384 + j * 4) = v;
    }
}

extern "C" void kernel_launch(void* const* d_in, const int* in_sizes, int n_in,
                              void* d_out, int out_size) {
    const float* x  = (const float*)d_in[0];   // [16,64,128,128]
    const float* ew = (const float*)d_in[1];   // [8,64,64,3,3]
    const float* eb = (const float*)d_in[2];   // [8,64]
    const float* gw = (const float*)d_in[3];   // [8,6144]
    const float* gb = (const float*)d_in[4];   // [8]
    float* out = (float*)d_out;                // [16,64,128,128]

    static bool attr_set = false;
    if (!attr_set) {
        cudaFuncSetAttribute(conv_mma,
                             cudaFuncAttributeMaxDynamicSharedMemorySize,
                             DSMEM_BYTES);
        attr_set = true;
    }

    prep_x<<<dim3(130, 16), 256>>>(x);
    prep_w<<<1152, 256>>>(ew);
    gate_kernel<<<4096, 256>>>(x, gw, gb);

    dim3 grid(128, 16);   // (row y, batch b)
    conv_mma<<<grid, 256, DSMEM_BYTES>>>(eb, out);
}